// round 1
// baseline (speedup 1.0000x reference)
#include <cuda_runtime.h>
#include <cuda_bf16.h>
#include <cstdint>

#define N_NEURONS 2048
#define BATCH     128
#define MEM       32
#define HID       256

__device__ __forceinline__ float sigmoidf_fast(float x) {
    // 1/(1+e^-x): MUFU.EX2 + MUFU.RCP path, ~2^-21 rel err
    return __fdividef(1.0f, 1.0f + __expf(-x));
}

__device__ __forceinline__ void mma_bf16(float c[4],
                                         uint32_t a0, uint32_t a1, uint32_t a2, uint32_t a3,
                                         uint32_t b0, uint32_t b1) {
    asm volatile(
        "mma.sync.aligned.m16n8k16.row.col.f32.bf16.bf16.f32 "
        "{%0,%1,%2,%3}, {%4,%5,%6,%7}, {%8,%9}, {%0,%1,%2,%3};"
        : "+f"(c[0]), "+f"(c[1]), "+f"(c[2]), "+f"(c[3])
        : "r"(a0), "r"(a1), "r"(a2), "r"(a3), "r"(b0), "r"(b1));
}

// Split two f32 into bf16 hi/lo packed pairs (x in low half, y in high half).
__device__ __forceinline__ void split_pack(float x, float y, uint32_t& hi, uint32_t& lo) {
    __nv_bfloat16 hx = __float2bfloat16(x);
    __nv_bfloat16 hy = __float2bfloat16(y);
    float rx = x - __bfloat162float(hx);
    float ry = y - __bfloat162float(hy);
    __nv_bfloat16 lx = __float2bfloat16(rx);
    __nv_bfloat16 ly = __float2bfloat16(ry);
    hi = ((uint32_t)__bfloat16_as_ushort(hy) << 16) | (uint32_t)__bfloat16_as_ushort(hx);
    lo = ((uint32_t)__bfloat16_as_ushort(ly) << 16) | (uint32_t)__bfloat16_as_ushort(lx);
}

__global__ __launch_bounds__(256, 2)
void nlm_kernel(const float* __restrict__ state,   // (128, 2048, 32)
                const float* __restrict__ w1,      // (2048, 32, 256)
                const float* __restrict__ b1,      // (2048, 256)
                const float* __restrict__ w2,      // (2048, 128, 2)
                const float* __restrict__ b2,      // (2048, 2)
                const float* __restrict__ Tg,      // (1,)
                float* __restrict__ out)           // (128, 2048)
{
    const int n    = blockIdx.x;
    const int tid  = threadIdx.x;
    const int w    = tid >> 5;     // warp 0..7, owns GLU cols [16w, 16w+16)
    const int lane = tid & 31;
    const int q    = lane & 3;
    const int lr   = lane >> 2;    // 0..7

    // X fragments: [mtile(8)][ks(2)][reg(4)][lane(32)], uint2 = {bf16x2 hi, bf16x2 lo}
    __shared__ uint2 XF[2048];                               // 16 KB
    __shared__ __align__(16) float b1s[256];                 // 1 KB
    __shared__ __align__(16) float w2s[256];                 // 1 KB  (h-major, o fastest)
    __shared__ __align__(16) float outPart[8 * 128 * 2];     // 8 KB

    // ---- B fragments (W1) loaded straight from global, once, into registers ----
    // Tiles per warp: a-side {2w, 2w+1}, b-side {2w+16, 2w+17} (GLU partner +128 cols)
    const float* W1g = w1 + (size_t)n * (MEM * HID);
    uint32_t BAhi[2][2][2], BAlo[2][2][2], BBhi[2][2][2], BBlo[2][2][2];
    #pragma unroll
    for (int p = 0; p < 2; p++) {
        const int tA = 2 * w + p;
        const int tB = tA + 16;
        #pragma unroll
        for (int ks = 0; ks < 2; ks++) {
            #pragma unroll
            for (int r = 0; r < 2; r++) {
                const int k = ks * 16 + r * 8 + 2 * q;
                {
                    const int col = tA * 8 + lr;
                    float v0 = W1g[k * HID + col];
                    float v1 = W1g[(k + 1) * HID + col];
                    split_pack(v0, v1, BAhi[p][ks][r], BAlo[p][ks][r]);
                }
                {
                    const int col = tB * 8 + lr;
                    float v0 = W1g[k * HID + col];
                    float v1 = W1g[(k + 1) * HID + col];
                    split_pack(v0, v1, BBhi[p][ks][r], BBlo[p][ks][r]);
                }
            }
        }
    }

    // ---- Stage X into bf16 hi/lo fragment layout (coalesced LDG.64) ----
    const float* Xg = state + (size_t)n * MEM;   // element (b, m) at b*65536 + m
    #pragma unroll
    for (int i = 0; i < 8; i++) {
        const int e   = tid + i * 256;
        const int el  = e & 31;
        const int reg = (e >> 5) & 3;
        const int ks  = (e >> 7) & 1;
        const int m   = e >> 8;
        const int brow = m * 16 + (el >> 2) + ((reg & 1) << 3);
        const int k    = ks * 16 + 2 * (el & 3) + ((reg & 2) << 2);
        float2 v = *reinterpret_cast<const float2*>(Xg + (size_t)brow * (N_NEURONS * MEM) + k);
        uint2 hl;
        split_pack(v.x, v.y, hl.x, hl.y);
        XF[e] = hl;
    }
    b1s[tid] = b1[n * 256 + tid];
    w2s[tid] = w2[n * 256 + tid];
    __syncthreads();

    // ---- Mainloop: each warp sweeps all 8 M-tiles with its 2 GLU column-pairs ----
    float* myPart = outPart + w * 256;
    for (int m = 0; m < 8; m++) {
        uint2 A[2][4];
        #pragma unroll
        for (int ks = 0; ks < 2; ks++)
            #pragma unroll
            for (int r = 0; r < 4; r++)
                A[ks][r] = XF[((m * 2 + ks) * 4 + r) * 32 + lane];

        float accLo0 = 0.f, accLo1 = 0.f, accHi0 = 0.f, accHi1 = 0.f;

        #pragma unroll
        for (int p = 0; p < 2; p++) {
            float Ca[4] = {0.f, 0.f, 0.f, 0.f};
            float Cb[4] = {0.f, 0.f, 0.f, 0.f};
            #pragma unroll
            for (int ks = 0; ks < 2; ks++) {
                const uint32_t ah0 = A[ks][0].x, ah1 = A[ks][1].x, ah2 = A[ks][2].x, ah3 = A[ks][3].x;
                const uint32_t al0 = A[ks][0].y, al1 = A[ks][1].y, al2 = A[ks][2].y, al3 = A[ks][3].y;
                // bf16x3: hi*hi + hi*lo + lo*hi, fp32 accumulate
                mma_bf16(Ca, ah0, ah1, ah2, ah3, BAhi[p][ks][0], BAhi[p][ks][1]);
                mma_bf16(Ca, ah0, ah1, ah2, ah3, BAlo[p][ks][0], BAlo[p][ks][1]);
                mma_bf16(Ca, al0, al1, al2, al3, BAhi[p][ks][0], BAhi[p][ks][1]);
                mma_bf16(Cb, ah0, ah1, ah2, ah3, BBhi[p][ks][0], BBhi[p][ks][1]);
                mma_bf16(Cb, ah0, ah1, ah2, ah3, BBlo[p][ks][0], BBlo[p][ks][1]);
                mma_bf16(Cb, al0, al1, al2, al3, BBhi[p][ks][0], BBhi[p][ks][1]);
            }
            // GLU1 + fused GEMM2 partial accumulation (all in registers)
            const int h0 = (2 * w + p) * 8 + 2 * q;        // g-column index (even)
            float2 ba = *reinterpret_cast<const float2*>(&b1s[h0]);
            float2 bb = *reinterpret_cast<const float2*>(&b1s[128 + h0]);
            Ca[0] += ba.x; Ca[1] += ba.y; Ca[2] += ba.x; Ca[3] += ba.y;
            Cb[0] += bb.x; Cb[1] += bb.y; Cb[2] += bb.x; Cb[3] += bb.y;
            const float g0 = Ca[0] * sigmoidf_fast(Cb[0]);
            const float g1 = Ca[1] * sigmoidf_fast(Cb[1]);
            const float g2 = Ca[2] * sigmoidf_fast(Cb[2]);
            const float g3 = Ca[3] * sigmoidf_fast(Cb[3]);
            float4 wv = *reinterpret_cast<const float4*>(&w2s[h0 * 2]);  // W2[h0..h0+1][0..1]
            accLo0 += g0 * wv.x + g1 * wv.z;
            accLo1 += g0 * wv.y + g1 * wv.w;
            accHi0 += g2 * wv.x + g3 * wv.z;
            accHi1 += g2 * wv.y + g3 * wv.w;
        }

        // quad reduce across the 4 lanes that share a row
        accLo0 += __shfl_xor_sync(0xffffffffu, accLo0, 1);
        accLo0 += __shfl_xor_sync(0xffffffffu, accLo0, 2);
        accLo1 += __shfl_xor_sync(0xffffffffu, accLo1, 1);
        accLo1 += __shfl_xor_sync(0xffffffffu, accLo1, 2);
        accHi0 += __shfl_xor_sync(0xffffffffu, accHi0, 1);
        accHi0 += __shfl_xor_sync(0xffffffffu, accHi0, 2);
        accHi1 += __shfl_xor_sync(0xffffffffu, accHi1, 1);
        accHi1 += __shfl_xor_sync(0xffffffffu, accHi1, 2);
        if (q == 0) {
            const int r0 = m * 16 + lr;
            myPart[r0 * 2 + 0]       = accLo0;
            myPart[r0 * 2 + 1]       = accLo1;
            myPart[(r0 + 8) * 2 + 0] = accHi0;
            myPart[(r0 + 8) * 2 + 1] = accHi1;
        }
    }

    __syncthreads();

    // ---- Final: sum 8 warp partials, GLU2, /T, store ----
    if (tid < BATCH) {
        float y0 = b2[n * 2 + 0];
        float y1 = b2[n * 2 + 1];
        #pragma unroll
        for (int ww = 0; ww < 8; ww++) {
            y0 += outPart[ww * 256 + tid * 2 + 0];
            y1 += outPart[ww * 256 + tid * 2 + 1];
        }
        float res = (y0 * sigmoidf_fast(y1)) / Tg[0];
        out[(size_t)tid * N_NEURONS + n] = res;
    }
}

extern "C" void kernel_launch(void* const* d_in, const int* in_sizes, int n_in,
                              void* d_out, int out_size) {
    const float* state = (const float*)d_in[0];
    const float* w1    = (const float*)d_in[1];
    const float* b1    = (const float*)d_in[2];
    const float* w2    = (const float*)d_in[3];
    const float* b2    = (const float*)d_in[4];
    const float* T     = (const float*)d_in[5];
    float* out = (float*)d_out;
    nlm_kernel<<<N_NEURONS, 256>>>(state, w1, b1, w2, b2, T, out);
}

// round 2
// speedup vs baseline: 1.0517x; 1.0517x over previous
#include <cuda_runtime.h>
#include <cuda_bf16.h>
#include <cstdint>

#define N_NEURONS 2048
#define BATCH     128
#define MEM       32
#define HID       256

// W1 f32 staging row stride in words: must be >=256 and == 4 (mod 16) so that
// fragment-gather LDS banks = (4k + col) mod 32 = 8q + lr + const -> 32 distinct.
#define W1S_STRIDE 260

// dynamic smem layout (bytes)
#define OFF_W1S   0
#define SZ_W1S    (32 * W1S_STRIDE * 4)          // 33280
#define OFF_XF    (OFF_W1S + SZ_W1S)             // 33280
#define SZ_XF     (2048 * 8)                     // 16384
#define OFF_B1    (OFF_XF + SZ_XF)               // 49664
#define OFF_W2    (OFF_B1 + 1024)                // 50688
#define OFF_PART  (OFF_W2 + 1024)                // 51712
#define SMEM_TOTAL (OFF_PART + 8192)             // 59904

__device__ __forceinline__ float sigmoidf_fast(float x) {
    return __fdividef(1.0f, 1.0f + __expf(-x));
}

__device__ __forceinline__ void mma_bf16(float c[4],
                                         uint32_t a0, uint32_t a1, uint32_t a2, uint32_t a3,
                                         uint32_t b0, uint32_t b1) {
    asm volatile(
        "mma.sync.aligned.m16n8k16.row.col.f32.bf16.bf16.f32 "
        "{%0,%1,%2,%3}, {%4,%5,%6,%7}, {%8,%9}, {%0,%1,%2,%3};"
        : "+f"(c[0]), "+f"(c[1]), "+f"(c[2]), "+f"(c[3])
        : "r"(a0), "r"(a1), "r"(a2), "r"(a3), "r"(b0), "r"(b1));
}

__device__ __forceinline__ void split_pack(float x, float y, uint32_t& hi, uint32_t& lo) {
    __nv_bfloat16 hx = __float2bfloat16(x);
    __nv_bfloat16 hy = __float2bfloat16(y);
    float rx = x - __bfloat162float(hx);
    float ry = y - __bfloat162float(hy);
    __nv_bfloat16 lx = __float2bfloat16(rx);
    __nv_bfloat16 ly = __float2bfloat16(ry);
    hi = ((uint32_t)__bfloat16_as_ushort(hy) << 16) | (uint32_t)__bfloat16_as_ushort(hx);
    lo = ((uint32_t)__bfloat16_as_ushort(ly) << 16) | (uint32_t)__bfloat16_as_ushort(lx);
}

__global__ __launch_bounds__(256, 2)
void nlm_kernel(const float* __restrict__ state,   // (128, 2048, 32)
                const float* __restrict__ w1,      // (2048, 32, 256)
                const float* __restrict__ b1,      // (2048, 256)
                const float* __restrict__ w2,      // (2048, 128, 2)
                const float* __restrict__ b2,      // (2048, 2)
                const float* __restrict__ Tg,      // (1,)
                float* __restrict__ out)           // (128, 2048)
{
    extern __shared__ char smem[];
    float* W1s     = (float*)(smem + OFF_W1S);
    uint2* XF      = (uint2*)(smem + OFF_XF);
    float* b1s     = (float*)(smem + OFF_B1);
    float* w2s     = (float*)(smem + OFF_W2);
    float* outPart = (float*)(smem + OFF_PART);

    const int n    = blockIdx.x;
    const int tid  = threadIdx.x;
    const int w    = tid >> 5;
    const int lane = tid & 31;
    const int q    = lane & 3;
    const int lr   = lane >> 2;

    // ---------------- Prologue: batched wide global loads ----------------
    const float* Xg  = state + (size_t)n * MEM;
    const float* W1g = w1 + (size_t)n * (MEM * HID);

    // X: 4 x LDG.128 per thread (coalesced: warp covers 4 rows x 128B lines)
    float4 xv[4];
    #pragma unroll
    for (int i = 0; i < 4; i++) {
        const int t    = tid + i * 256;
        const int s    = t & 7;          // float4 index within row (k0 = 4s)
        const int brow = t >> 3;         // batch row 0..127
        xv[i] = *reinterpret_cast<const float4*>(Xg + (size_t)brow * (N_NEURONS * MEM) + 4 * s);
    }
    // W1: 8 x LDG.128 per thread, fully coalesced
    float4 wv[8];
    #pragma unroll
    for (int i = 0; i < 8; i++) {
        const int t  = tid + i * 256;
        const int c4 = t & 63;
        const int k  = t >> 6;
        wv[i] = *reinterpret_cast<const float4*>(W1g + k * HID + 4 * c4);
    }
    const float b1v = b1[n * 256 + tid];
    const float w2v = w2[n * 256 + tid];

    // Convert X -> fragment layout, STS.128
    #pragma unroll
    for (int i = 0; i < 4; i++) {
        const int t    = tid + i * 256;
        const int s    = t & 7;
        const int brow = t >> 3;
        const int p0   = 2 * s;                 // even k-pair index
        const int q0   = p0 & 3;                // even
        const int reg2 = (p0 >> 2) & 1;
        const int ks   = p0 >> 3;
        const int flr  = brow & 7;
        const int reg  = ((brow >> 3) & 1) + 2 * reg2;
        const int m    = brow >> 4;
        const int idx  = ((m * 2 + ks) * 4 + reg) * 32 + flr * 4 + q0;
        uint4 hl;
        split_pack(xv[i].x, xv[i].y, hl.x, hl.y);
        split_pack(xv[i].z, xv[i].w, hl.z, hl.w);
        *reinterpret_cast<uint4*>(&XF[idx]) = hl;
    }
    // Stage W1 raw f32 into padded smem
    #pragma unroll
    for (int i = 0; i < 8; i++) {
        const int t  = tid + i * 256;
        const int c4 = t & 63;
        const int k  = t >> 6;
        *reinterpret_cast<float4*>(&W1s[k * W1S_STRIDE + 4 * c4]) = wv[i];
    }
    b1s[tid] = b1v;
    w2s[tid] = w2v;
    __syncthreads();

    // ---------------- Build B (W1) fragments from smem (conflict-free) ----------------
    uint32_t BAhi[2][2][2], BAlo[2][2][2], BBhi[2][2][2], BBlo[2][2][2];
    #pragma unroll
    for (int p = 0; p < 2; p++) {
        const int tA = 2 * w + p;
        const int colA = tA * 8 + lr;
        const int colB = colA + 128;
        #pragma unroll
        for (int ks = 0; ks < 2; ks++) {
            #pragma unroll
            for (int r = 0; r < 2; r++) {
                const int k = ks * 16 + r * 8 + 2 * q;
                float a0 = W1s[k * W1S_STRIDE + colA];
                float a1 = W1s[(k + 1) * W1S_STRIDE + colA];
                split_pack(a0, a1, BAhi[p][ks][r], BAlo[p][ks][r]);
                float c0 = W1s[k * W1S_STRIDE + colB];
                float c1 = W1s[(k + 1) * W1S_STRIDE + colB];
                split_pack(c0, c1, BBhi[p][ks][r], BBlo[p][ks][r]);
            }
        }
    }

    // ---------------- Mainloop ----------------
    float* myPart = outPart + w * 256;
    for (int m = 0; m < 8; m++) {
        uint2 A[2][4];
        #pragma unroll
        for (int ks = 0; ks < 2; ks++)
            #pragma unroll
            for (int r = 0; r < 4; r++)
                A[ks][r] = XF[((m * 2 + ks) * 4 + r) * 32 + lane];

        float accLo0 = 0.f, accLo1 = 0.f, accHi0 = 0.f, accHi1 = 0.f;

        #pragma unroll
        for (int p = 0; p < 2; p++) {
            float Ca[4] = {0.f, 0.f, 0.f, 0.f};
            float Cb[4] = {0.f, 0.f, 0.f, 0.f};
            #pragma unroll
            for (int ks = 0; ks < 2; ks++) {
                const uint32_t ah0 = A[ks][0].x, ah1 = A[ks][1].x, ah2 = A[ks][2].x, ah3 = A[ks][3].x;
                const uint32_t al0 = A[ks][0].y, al1 = A[ks][1].y, al2 = A[ks][2].y, al3 = A[ks][3].y;
                mma_bf16(Ca, ah0, ah1, ah2, ah3, BAhi[p][ks][0], BAhi[p][ks][1]);
                mma_bf16(Ca, ah0, ah1, ah2, ah3, BAlo[p][ks][0], BAlo[p][ks][1]);
                mma_bf16(Ca, al0, al1, al2, al3, BAhi[p][ks][0], BAhi[p][ks][1]);
                mma_bf16(Cb, ah0, ah1, ah2, ah3, BBhi[p][ks][0], BBhi[p][ks][1]);
                mma_bf16(Cb, ah0, ah1, ah2, ah3, BBlo[p][ks][0], BBlo[p][ks][1]);
                mma_bf16(Cb, al0, al1, al2, al3, BBhi[p][ks][0], BBhi[p][ks][1]);
            }
            const int h0 = (2 * w + p) * 8 + 2 * q;
            float2 ba = *reinterpret_cast<const float2*>(&b1s[h0]);
            float2 bb = *reinterpret_cast<const float2*>(&b1s[128 + h0]);
            Ca[0] += ba.x; Ca[1] += ba.y; Ca[2] += ba.x; Ca[3] += ba.y;
            Cb[0] += bb.x; Cb[1] += bb.y; Cb[2] += bb.x; Cb[3] += bb.y;
            const float g0 = Ca[0] * sigmoidf_fast(Cb[0]);
            const float g1 = Ca[1] * sigmoidf_fast(Cb[1]);
            const float g2 = Ca[2] * sigmoidf_fast(Cb[2]);
            const float g3 = Ca[3] * sigmoidf_fast(Cb[3]);
            float4 w2f = *reinterpret_cast<const float4*>(&w2s[h0 * 2]);
            accLo0 += g0 * w2f.x + g1 * w2f.z;
            accLo1 += g0 * w2f.y + g1 * w2f.w;
            accHi0 += g2 * w2f.x + g3 * w2f.z;
            accHi1 += g2 * w2f.y + g3 * w2f.w;
        }

        accLo0 += __shfl_xor_sync(0xffffffffu, accLo0, 1);
        accLo0 += __shfl_xor_sync(0xffffffffu, accLo0, 2);
        accLo1 += __shfl_xor_sync(0xffffffffu, accLo1, 1);
        accLo1 += __shfl_xor_sync(0xffffffffu, accLo1, 2);
        accHi0 += __shfl_xor_sync(0xffffffffu, accHi0, 1);
        accHi0 += __shfl_xor_sync(0xffffffffu, accHi0, 2);
        accHi1 += __shfl_xor_sync(0xffffffffu, accHi1, 1);
        accHi1 += __shfl_xor_sync(0xffffffffu, accHi1, 2);
        if (q == 0) {
            const int r0 = m * 16 + lr;
            myPart[r0 * 2 + 0]       = accLo0;
            myPart[r0 * 2 + 1]       = accLo1;
            myPart[(r0 + 8) * 2 + 0] = accHi0;
            myPart[(r0 + 8) * 2 + 1] = accHi1;
        }
    }

    __syncthreads();

    if (tid < BATCH) {
        float y0 = b2[n * 2 + 0];
        float y1 = b2[n * 2 + 1];
        #pragma unroll
        for (int ww = 0; ww < 8; ww++) {
            y0 += outPart[ww * 256 + tid * 2 + 0];
            y1 += outPart[ww * 256 + tid * 2 + 1];
        }
        float res = (y0 * sigmoidf_fast(y1)) / Tg[0];
        out[(size_t)tid * N_NEURONS + n] = res;
    }
}

extern "C" void kernel_launch(void* const* d_in, const int* in_sizes, int n_in,
                              void* d_out, int out_size) {
    const float* state = (const float*)d_in[0];
    const float* w1    = (const float*)d_in[1];
    const float* b1    = (const float*)d_in[2];
    const float* w2    = (const float*)d_in[3];
    const float* b2    = (const float*)d_in[4];
    const float* T     = (const float*)d_in[5];
    float* out = (float*)d_out;
    cudaFuncSetAttribute(nlm_kernel, cudaFuncAttributeMaxDynamicSharedMemorySize, SMEM_TOTAL);
    nlm_kernel<<<N_NEURONS, 256, SMEM_TOTAL>>>(state, w1, b1, w2, b2, T, out);
}